// round 3
// baseline (speedup 1.0000x reference)
#include <cuda_runtime.h>
#include <math.h>

#define NB 128    // batch
#define TT 2000   // attention time steps
#define LL 250    // decode length
#define HH 512    // hidden
#define KK 128    // key size
#define VV 128    // value size
#define AA 64     // alphabet
#define NBLK 256
#define NTHR 256

// ---------------- device scratch (feature-major state) ----------------
__device__ float g_Pb[64 * 2048];            // token -> gate base (emb@W + biases)
__device__ float g_h1T[2 * HH * NB];         // double-buffered
__device__ float g_c1T[HH * NB];
__device__ float g_h2T[2 * KK * NB];         // double-buffered
__device__ float g_c2T[KK * NB];
__device__ float g_ctxT[VV * NB];
__device__ float g_pm[NB * 2], g_ps[NB * 2], g_pacc[NB * 2 * VV];
__device__ int   g_acnt[NB];
__device__ unsigned g_gen, g_cnt;            // grid barrier (monotonic gen)

__device__ __forceinline__ float sigf(float x) { return 1.0f / (1.0f + __expf(-x)); }
__device__ __forceinline__ float dot4w(float4 a, float4 b) {
    return a.x * b.x + a.y * b.y + a.z * b.z + a.w * b.w;
}

// sense-free monotonic grid barrier; all NBLK blocks are resident by construction
__device__ __forceinline__ void gbar() {
    __syncthreads();
    __threadfence();
    if (threadIdx.x == 0) {
        unsigned my = *(volatile unsigned*)&g_gen;
        unsigned old = atomicAdd(&g_cnt, 1u);
        if (old == NBLK - 1) {
            g_cnt = 0u;
            __threadfence();
            atomicAdd(&g_gen, 1u);
        } else {
            while (*(volatile unsigned*)&g_gen == my) { __nanosleep(64); }
        }
        __threadfence();
    }
    __syncthreads();
}

// ---------------- init ----------------
__global__ void init_kernel(const float* __restrict__ values) {
    int i = blockIdx.x * 256 + threadIdx.x;        // grid 256 -> 65536 threads
    if (i < HH * NB) { g_h1T[i] = 0.0f; g_c1T[i] = 0.0f; }
    if (i < KK * NB) {
        g_h2T[i] = 0.0f; g_c2T[i] = 0.0f;
        int v = i >> 7, n = i & 127;
        g_ctxT[(size_t)v * NB + n] = values[n * VV + v];   // ctx0 = values[0]
    }
    if (i < NB) g_acnt[i] = 0;
}

// ------------- Pb = emb @ W_ih1[:, :512]^T + b_ih1 + b_hh1  (64 x 2048) ----
__global__ __launch_bounds__(256) void pb_kernel(
    const float* __restrict__ emb, const float* __restrict__ W_ih1,
    const float* __restrict__ b_ih1, const float* __restrict__ b_hh1)
{
    const int c0 = blockIdx.x * 32;                 // 64 blocks
    const int col = threadIdx.x & 31, rg = threadIdx.x >> 5;
    const int ca = c0 + col;
    float acc[8];
#pragma unroll
    for (int i = 0; i < 8; i++) acc[i] = 0.0f;
    for (int k = 0; k < HH; k++) {
        float w = W_ih1[(size_t)ca * 640 + k];
#pragma unroll
        for (int i = 0; i < 8; i++)
            acc[i] = fmaf(emb[(size_t)(rg * 8 + i) * HH + k], w, acc[i]);
    }
    float bb = b_ih1[ca] + b_hh1[ca];
#pragma unroll
    for (int i = 0; i < 8; i++)
        g_Pb[(size_t)(rg * 8 + i) * 2048 + ca] = acc[i] + bb;
}

// ---------------- persistent main kernel ----------------
struct SAs {
    float Xs[16][128];
    float sg[8][132];
    int toks[128];
};
struct SCs {
    float h2s[128];
    float wacc[8][128];
    float wm[8], wsum[8];
    float ctxs[128];
    int islast;
};

__global__ __launch_bounds__(NTHR, 2) void decoder_main(
    const float* __restrict__ key, const float* __restrict__ val,
    const int* __restrict__ lens, const int* __restrict__ text,
    const float* __restrict__ W_ih1, const float* __restrict__ W_hh1,
    const float* __restrict__ W_ih2, const float* __restrict__ W_hh2,
    const float* __restrict__ b_ih2, const float* __restrict__ b_hh2,
    const float* __restrict__ W_mos, const float* __restrict__ b_mos,
    float* __restrict__ out)
{
    __shared__ float WsA[8][644];     // LSTM1: this block's 8 gate rows (K=640)
    __shared__ float WsB[4][644];     // LSTM2: this block's 4 gate rows (blk<128)
    __shared__ union { SAs a; SCs c; } scr;

    const int blk = blockIdx.x;
    const int tid = threadIdx.x;

    // ---- one-time weight preload into smem (persists across all steps) ----
#pragma unroll 1
    for (int it = 0; it < 20; it++) {
        int idx = it * 256 + tid;              // 8 * 640 = 5120
        int c = idx / 640, k = idx - c * 640;
        int ca = ((c & 3) << 9) + (blk << 1) + (c >> 2);   // gate*512 + unit
        WsA[c][k] = (k < VV) ? W_ih1[(size_t)ca * 640 + 512 + k]
                             : W_hh1[(size_t)ca * 512 + (k - VV)];
    }
    if (blk < 128) {
#pragma unroll 1
        for (int it = 0; it < 10; it++) {
            int idx = it * 256 + tid;          // 4 * 640 = 2560
            int c = idx / 640, k = idx - c * 640;
            int ca = c * 128 + blk;            // gate*128 + unit
            WsB[c][k] = (k < HH) ? W_ih2[(size_t)ca * HH + k]
                                 : W_hh2[(size_t)ca * KK + (k - HH)];
        }
    }
    __syncthreads();

    for (int l = 0; l < LL; l++) {
        const int p = l & 1;

        // ================= phase A: LSTM1 gates + apply =================
        {
            SAs& sa = scr.a;
            if (tid < NB) sa.toks[tid] = text[tid * LL + l];
            __syncthreads();
            const int col = tid & 7, ng = tid >> 3;
            const int ca = ((col & 3) << 9) + (blk << 1) + (col >> 2);
            float acc0 = g_Pb[(size_t)sa.toks[(ng << 2) + 0] * 2048 + ca];
            float acc1 = g_Pb[(size_t)sa.toks[(ng << 2) + 1] * 2048 + ca];
            float acc2 = g_Pb[(size_t)sa.toks[(ng << 2) + 2] * 2048 + ca];
            float acc3 = g_Pb[(size_t)sa.toks[(ng << 2) + 3] * 2048 + ca];
            const float* h1r = g_h1T + (size_t)p * (HH * NB);
#pragma unroll 1
            for (int ch = 0; ch < 40; ch++) {
                const int kb = ch << 4;
                __syncthreads();
#pragma unroll
                for (int it = 0; it < 8; it++) {
                    int idx = (it << 8) + tid;
                    int k = idx >> 7, nn = idx & 127;
                    int kg = kb + k;
                    sa.Xs[k][nn] = (kg < VV) ? __ldcg(&g_ctxT[(size_t)kg * NB + nn])
                                             : __ldcg(&h1r[(size_t)(kg - VV) * NB + nn]);
                }
                __syncthreads();
#pragma unroll
                for (int k = 0; k < 16; k++) {
                    float w = WsA[col][kb + k];
                    acc0 = fmaf(sa.Xs[k][(ng << 2) + 0], w, acc0);
                    acc1 = fmaf(sa.Xs[k][(ng << 2) + 1], w, acc1);
                    acc2 = fmaf(sa.Xs[k][(ng << 2) + 2], w, acc2);
                    acc3 = fmaf(sa.Xs[k][(ng << 2) + 3], w, acc3);
                }
            }
            __syncthreads();
            sa.sg[col][(ng << 2) + 0] = acc0;
            sa.sg[col][(ng << 2) + 1] = acc1;
            sa.sg[col][(ng << 2) + 2] = acc2;
            sa.sg[col][(ng << 2) + 3] = acc3;
            __syncthreads();
            // apply: thread -> (n, unit)
            const int nn = tid & 127, u = tid >> 7;
            float gi = sa.sg[(u << 2) + 0][nn];
            float gf = sa.sg[(u << 2) + 1][nn];
            float gg = sa.sg[(u << 2) + 2][nn];
            float go = sa.sg[(u << 2) + 3][nn];
            int ci = ((blk << 1) + u) * NB + nn;
            float cn = sigf(gf) * g_c1T[ci] + sigf(gi) * tanhf(gg);
            g_c1T[ci] = cn;
            g_h1T[(size_t)(p ^ 1) * (HH * NB) + ci] = sigf(go) * tanhf(cn);
        }
        gbar();

        // ================= phase B: LSTM2 gates + apply =================
        if (blk < 128) {
            SAs& sa = scr.a;
            const int col = tid & 3, ng = tid >> 2;
            float acc0 = 0.0f, acc1 = 0.0f;
            const float* h1r = g_h1T + (size_t)(p ^ 1) * (HH * NB);
            const float* h2r = g_h2T + (size_t)p * (KK * NB);
#pragma unroll 1
            for (int ch = 0; ch < 40; ch++) {
                const int kb = ch << 4;
                __syncthreads();
#pragma unroll
                for (int it = 0; it < 8; it++) {
                    int idx = (it << 8) + tid;
                    int k = idx >> 7, nn = idx & 127;
                    int kg = kb + k;
                    sa.Xs[k][nn] = (kg < HH) ? __ldcg(&h1r[(size_t)kg * NB + nn])
                                             : __ldcg(&h2r[(size_t)(kg - HH) * NB + nn]);
                }
                __syncthreads();
#pragma unroll
                for (int k = 0; k < 16; k++) {
                    float w = WsB[col][kb + k];
                    acc0 = fmaf(sa.Xs[k][(ng << 1) + 0], w, acc0);
                    acc1 = fmaf(sa.Xs[k][(ng << 1) + 1], w, acc1);
                }
            }
            __syncthreads();
            sa.sg[col][(ng << 1) + 0] = acc0;
            sa.sg[col][(ng << 1) + 1] = acc1;
            __syncthreads();
            if (tid < 128) {
                const int nn = tid;
                float gi = sa.sg[0][nn] + b_ih2[blk] + b_hh2[blk];
                float gf = sa.sg[1][nn] + b_ih2[128 + blk] + b_hh2[128 + blk];
                float gg = sa.sg[2][nn] + b_ih2[256 + blk] + b_hh2[256 + blk];
                float go = sa.sg[3][nn] + b_ih2[384 + blk] + b_hh2[384 + blk];
                int ci = blk * NB + nn;
                float cn = sigf(gf) * g_c2T[ci] + sigf(gi) * tanhf(gg);
                g_c2T[ci] = cn;
                g_h2T[(size_t)(p ^ 1) * (KK * NB) + ci] = sigf(go) * tanhf(cn);
            }
        }
        gbar();

        // ========== phase C: attention partial + fused combine/MoS ==========
        {
            SCs& sc = scr.c;
            const int n = blk >> 1, sp = blk & 1;
            const int len = lens[n];
            const int half = (len + 1) >> 1;
            const int t0 = sp * half;
            const int t1 = min(len, t0 + half);
            const int warp = tid >> 5, lane = tid & 31;

            if (tid < KK)
                sc.h2s[tid] = __ldcg(&g_h2T[(size_t)(p ^ 1) * (KK * NB) + tid * NB + n]);
            __syncthreads();
            const float4 hv = *(const float4*)&sc.h2s[lane << 2];

            float m = -1e30f, ssum = 0.0f;
            float4 acc = make_float4(0.f, 0.f, 0.f, 0.f);
            const size_t trow = (size_t)NB * KK;

            int t = t0 + warp;
            for (; t + 24 < t1; t += 32) {
                const size_t b0 = (size_t)t * trow + (size_t)n * KK + (lane << 2);
                float4 ka = *(const float4*)(key + b0);
                float4 kb = *(const float4*)(key + b0 + 8 * trow);
                float4 kc = *(const float4*)(key + b0 + 16 * trow);
                float4 kd = *(const float4*)(key + b0 + 24 * trow);
                float4 va = *(const float4*)(val + b0);
                float4 vb = *(const float4*)(val + b0 + 8 * trow);
                float4 vc = *(const float4*)(val + b0 + 16 * trow);
                float4 vd = *(const float4*)(val + b0 + 24 * trow);
                float d0 = dot4w(ka, hv), d1 = dot4w(kb, hv);
                float d2 = dot4w(kc, hv), d3 = dot4w(kd, hv);
#pragma unroll
                for (int o = 16; o; o >>= 1) {
                    d0 += __shfl_xor_sync(0xffffffffu, d0, o);
                    d1 += __shfl_xor_sync(0xffffffffu, d1, o);
                    d2 += __shfl_xor_sync(0xffffffffu, d2, o);
                    d3 += __shfl_xor_sync(0xffffffffu, d3, o);
                }
                float mx = fmaxf(fmaxf(d0, d1), fmaxf(d2, d3));
                float mn = fmaxf(m, mx);
                float scale = __expf(m - mn);
                float p0 = __expf(d0 - mn), p1 = __expf(d1 - mn);
                float p2 = __expf(d2 - mn), p3 = __expf(d3 - mn);
                ssum = ssum * scale + ((p0 + p1) + (p2 + p3));
                acc.x = acc.x * scale + p0 * va.x + p1 * vb.x + p2 * vc.x + p3 * vd.x;
                acc.y = acc.y * scale + p0 * va.y + p1 * vb.y + p2 * vc.y + p3 * vd.y;
                acc.z = acc.z * scale + p0 * va.z + p1 * vb.z + p2 * vc.z + p3 * vd.z;
                acc.w = acc.w * scale + p0 * va.w + p1 * vb.w + p2 * vc.w + p3 * vd.w;
                m = mn;
            }
            for (; t < t1; t += 8) {
                const size_t b0 = (size_t)t * trow + (size_t)n * KK + (lane << 2);
                float4 k4 = *(const float4*)(key + b0);
                float4 v4 = *(const float4*)(val + b0);
                float d = dot4w(k4, hv);
#pragma unroll
                for (int o = 16; o; o >>= 1) d += __shfl_xor_sync(0xffffffffu, d, o);
                float mn = fmaxf(m, d);
                float scale = __expf(m - mn);
                float pp = __expf(d - mn);
                ssum = ssum * scale + pp;
                acc.x = acc.x * scale + pp * v4.x;
                acc.y = acc.y * scale + pp * v4.y;
                acc.z = acc.z * scale + pp * v4.z;
                acc.w = acc.w * scale + pp * v4.w;
                m = mn;
            }

            if (lane == 0) { sc.wm[warp] = m; sc.wsum[warp] = ssum; }
            *(float4*)&sc.wacc[warp][lane << 2] = acc;
            __syncthreads();

            if (tid < VV) {
                float mm = -1e30f;
#pragma unroll
                for (int w = 0; w < 8; w++) mm = fmaxf(mm, sc.wm[w]);
                float S = 0.0f, C = 0.0f;
#pragma unroll
                for (int w = 0; w < 8; w++) {
                    float e = __expf(sc.wm[w] - mm);
                    S += e * sc.wsum[w];
                    C += e * sc.wacc[w][tid];
                }
                g_pacc[(size_t)(n * 2 + sp) * VV + tid] = C;
                if (tid == 0) { g_pm[n * 2 + sp] = mm; g_ps[n * 2 + sp] = S; }
                __threadfence();
            }
            __syncthreads();
            if (tid == 0) {
                int old = atomicAdd(&g_acnt[n], 1);
                __threadfence();
                sc.islast = (old == 1);
            }
            __syncthreads();
            if (sc.islast) {
                if (tid < VV) {
                    float m0 = __ldcg(&g_pm[n * 2]), m1 = __ldcg(&g_pm[n * 2 + 1]);
                    float mm = fmaxf(m0, m1);
                    float e0 = __expf(m0 - mm), e1 = __expf(m1 - mm);
                    float S = e0 * __ldcg(&g_ps[n * 2]) + e1 * __ldcg(&g_ps[n * 2 + 1]);
                    float C = e0 * __ldcg(&g_pacc[(size_t)(n * 2) * VV + tid]) +
                              e1 * __ldcg(&g_pacc[(size_t)(n * 2 + 1) * VV + tid]);
                    float cv = C / S;
                    sc.ctxs[tid] = cv;
                    g_ctxT[(size_t)tid * NB + n] = cv;
                }
                if (tid == 0) g_acnt[n] = 0;
                __syncthreads();
                if (tid < AA) {
                    float a = b_mos[tid];
                    const float* w = W_mos + (size_t)tid * (KK + VV);
#pragma unroll 4
                    for (int k = 0; k < KK; k++) a = fmaf(sc.h2s[k], w[k], a);
#pragma unroll 4
                    for (int v = 0; v < VV; v++) a = fmaf(sc.ctxs[v], w[KK + v], a);
                    out[((size_t)n * LL + l) * AA + tid] = a;
                }
            }
        }
        gbar();
    }
}

// ---------------- launch ----------------
extern "C" void kernel_launch(void* const* d_in, const int* in_sizes, int n_in,
                              void* d_out, int out_size) {
    (void)in_sizes; (void)n_in; (void)out_size;
    const float* key    = (const float*)d_in[0];
    const float* values = (const float*)d_in[1];
    const int*   lens   = (const int*)  d_in[2];
    const int*   text   = (const int*)  d_in[3];
    const float* emb    = (const float*)d_in[4];
    const float* W_ih1  = (const float*)d_in[5];
    const float* W_hh1  = (const float*)d_in[6];
    const float* b_ih1  = (const float*)d_in[7];
    const float* b_hh1  = (const float*)d_in[8];
    const float* W_ih2  = (const float*)d_in[9];
    const float* W_hh2  = (const float*)d_in[10];
    const float* b_ih2  = (const float*)d_in[11];
    const float* b_hh2  = (const float*)d_in[12];
    const float* W_mos  = (const float*)d_in[13];
    const float* b_mos  = (const float*)d_in[14];
    float* out = (float*)d_out;

    init_kernel<<<256, 256>>>(values);
    pb_kernel<<<64, 256>>>(emb, W_ih1, b_ih1, b_hh1);
    decoder_main<<<NBLK, NTHR>>>(key, values, lens, text,
                                 W_ih1, W_hh1, W_ih2, W_hh2,
                                 b_ih2, b_hh2, W_mos, b_mos, out);
}

// round 6
// speedup vs baseline: 1.0851x; 1.0851x over previous
#include <cuda_runtime.h>
#include <cuda_fp16.h>
#include <math.h>

#define NB 128    // batch
#define TT 2000   // attention time steps
#define LL 250    // decode length
#define HH 512    // hidden
#define KK 128    // key size
#define VV 128    // value size
#define AA 64     // alphabet
#define NBLK 256
#define NTHR 256

// ---------------- device scratch ----------------
__device__ __half g_kb[(size_t)TT * NB * KK];          // fp16 keys   (65.5 MB)
__device__ __half g_vb[(size_t)TT * NB * VV];          // fp16 values (65.5 MB)
__device__ float g_PbT[2048 * 64];                     // transposed token gate-base
__device__ float g_h1T[2 * HH * NB], g_c1T[HH * NB];   // feature-major state
__device__ float g_h2T[2 * KK * NB], g_c2T[KK * NB];
__device__ float g_ctxT[VV * NB];
__device__ float g_pm[NB * NBLK], g_ps[NB * NBLK];
__device__ float g_pacc[(size_t)NB * NBLK * VV];       // 16.8 MB
__device__ int   g_acnt[NB];
__device__ int   g_prefix[NB + 1];
__device__ int   g_bfirst[NB], g_blast[NB], g_bcnt[NB];
__device__ unsigned g_gen, g_cnt;

__device__ __forceinline__ float sigf(float x) { return 1.0f / (1.0f + __expf(-x)); }

__device__ __forceinline__ void gbar() {
    __syncthreads();
    __threadfence();
    if (threadIdx.x == 0) {
        unsigned my = *(volatile unsigned*)&g_gen;
        unsigned old = atomicAdd(&g_cnt, 1u);
        if (old == NBLK - 1) {
            g_cnt = 0u;
            __threadfence();
            atomicAdd(&g_gen, 1u);
        } else {
            while (*(volatile unsigned*)&g_gen == my) { __nanosleep(64); }
        }
        __threadfence();
    }
    __syncthreads();
}

// ---------------- init ----------------
__global__ void init_kernel(const float* __restrict__ values) {
    int i = blockIdx.x * 256 + threadIdx.x;          // 65536 threads
    if (i < HH * NB) { g_h1T[i] = 0.0f; g_c1T[i] = 0.0f;
                       g_h1T[HH * NB + i] = 0.0f; }
    if (i < KK * NB) {
        g_h2T[i] = 0.0f; g_c2T[i] = 0.0f; g_h2T[KK * NB + i] = 0.0f;
        int v = i >> 7, n = i & 127;
        g_ctxT[v * NB + n] = values[n * VV + v];      // ctx0 = values[0]
    }
    if (i < NB) g_acnt[i] = 0;
}

// ---------------- meta: prefix sums + per-n block coverage ----------------
__global__ void meta_kernel(const int* __restrict__ lens) {
    __shared__ int pre[NB + 1];
    if (threadIdx.x == 0) {
        int s = 0;
        for (int n = 0; n < NB; n++) { pre[n] = s; s += lens[n]; }
        pre[NB] = s;
        for (int i = 0; i <= NB; i++) g_prefix[i] = pre[i];
    }
    __syncthreads();
    int n = threadIdx.x;
    if (n < NB) {
        long long W = pre[NB];
        int Pn = pre[n], Pn1 = pre[n + 1];
        int bf = 0, bl = 0, cnt = 0;
        for (int b = 0; b < NBLK; b++) {
            int r0 = (int)((long long)b * W / NBLK);
            int r1 = (int)((long long)(b + 1) * W / NBLK);
            int lo = max(r0, Pn), hi = min(r1, Pn1);
            if (lo < hi) { if (cnt == 0) bf = b; bl = b; cnt++; }
        }
        g_bfirst[n] = bf; g_blast[n] = bl; g_bcnt[n] = cnt;
    }
}

// ---------------- fp16 conversion ----------------
__global__ void conv_kernel(const float* __restrict__ key, const float* __restrict__ val) {
    size_t stride = (size_t)gridDim.x * blockDim.x;
    for (size_t i = (size_t)blockIdx.x * blockDim.x + threadIdx.x;
         i < (size_t)TT * NB * KK; i += stride) {
        g_kb[i] = __float2half(key[i]);
        g_vb[i] = __float2half(val[i]);
    }
}

// ------------- PbT[ca][tok] = (emb @ W_ih1[:, :512]^T + b_ih1 + b_hh1)^T ----
__global__ __launch_bounds__(256) void pb_kernel(
    const float* __restrict__ emb, const float* __restrict__ W_ih1,
    const float* __restrict__ b_ih1, const float* __restrict__ b_hh1)
{
    const int c0 = blockIdx.x * 32;                  // 64 blocks
    const int col = threadIdx.x & 31, rg = threadIdx.x >> 5;
    const int ca = c0 + col;
    float acc[8];
#pragma unroll
    for (int i = 0; i < 8; i++) acc[i] = 0.0f;
    for (int k = 0; k < HH; k++) {
        float w = W_ih1[(size_t)ca * 640 + k];
#pragma unroll
        for (int i = 0; i < 8; i++)
            acc[i] = fmaf(emb[(size_t)(rg * 8 + i) * HH + k], w, acc[i]);
    }
    float bb = b_ih1[ca] + b_hh1[ca];
#pragma unroll
    for (int i = 0; i < 8; i++)
        g_PbT[(size_t)ca * 64 + rg * 8 + i] = acc[i] + bb;
}

// ---------------- persistent main kernel ----------------
struct SA {                    // phase A scratch (vector-read arrays 16B-aligned)
    float Xs[16][64];
    float Ws[16][17];
    float sg[16][68];
    int toks[64];
};
struct SB {                    // phase B scratch
    float Xs[16][128];
    float sg[4][132];
};
struct SC {                    // phase C scratch — float4-accessed arrays FIRST
    float h2s[KK];             // offset 0
    float wacc[8][VV];         // offset 512 (16B-aligned)
    float ctxs[VV];
    float wm[8], wsum[8];
    int   prefix[NB + 1];      // scalar-only access; keep after vector arrays
    int   flag;
};

__global__ __launch_bounds__(NTHR, 2) void decoder_main(
    const int* __restrict__ text,
    const float* __restrict__ W_ih1, const float* __restrict__ W_hh1,
    const float* __restrict__ W_ih2, const float* __restrict__ W_hh2,
    const float* __restrict__ b_ih2, const float* __restrict__ b_hh2,
    const float* __restrict__ W_mos, const float* __restrict__ b_mos,
    float* __restrict__ out)
{
    __shared__ float WsB[4][644];
    __shared__ __align__(16) union { SA a; SB b; SC c; } scr;

    const int blk = blockIdx.x;
    const int tid = threadIdx.x;

    // one-time LSTM2 weight preload (blocks < 128)
    if (blk < 128) {
#pragma unroll 1
        for (int it = 0; it < 10; it++) {
            int idx = it * 256 + tid;                // 4*640
            int c = idx / 640, k = idx - c * 640;
            int ca = c * 128 + blk;
            WsB[c][k] = (k < HH) ? W_ih2[(size_t)ca * HH + k]
                                 : W_hh2[(size_t)ca * KK + (k - HH)];
        }
    }
    __syncthreads();

    for (int l = 0; l < LL; l++) {
        const int p = l & 1;

        // ===== phase A: LSTM1 gates (16 cols x 64 n per block) + apply =====
        {
            SA& sa = scr.a;
            const int ct = blk >> 1, nh = blk & 1, u0 = ct * 4;
            if (tid < 64) sa.toks[tid] = text[(nh * 64 + tid) * LL + l];
            const int col = tid & 15, ng = tid >> 4;
            const int caC = ((col & 3) << 9) + u0 + (col >> 2);
            const int kW = tid & 15, cW = tid >> 4;
            const int caW = ((cW & 3) << 9) + u0 + (cW >> 2);
            const int nn = tid & 63, kofs = tid >> 6;
            const int gn = nh * 64 + nn;
            const float* h1r = g_h1T + (size_t)p * (HH * NB);
            __syncthreads();

            float acc0 = g_PbT[(size_t)caC * 64 + sa.toks[(ng << 2) + 0]];
            float acc1 = g_PbT[(size_t)caC * 64 + sa.toks[(ng << 2) + 1]];
            float acc2 = g_PbT[(size_t)caC * 64 + sa.toks[(ng << 2) + 2]];
            float acc3 = g_PbT[(size_t)caC * 64 + sa.toks[(ng << 2) + 3]];

            float xr[4], wr;
#pragma unroll
            for (int it = 0; it < 4; it++) {
                int kg = kofs + (it << 2);
                xr[it] = (kg < VV) ? __ldcg(&g_ctxT[kg * NB + gn])
                                   : __ldcg(&h1r[(kg - VV) * NB + gn]);
            }
            wr = (kW < VV) ? W_ih1[(size_t)caW * 640 + 512 + kW]
                           : W_hh1[(size_t)caW * 512 + (kW - VV)];

#pragma unroll 1
            for (int ch = 0; ch < 40; ch++) {
                __syncthreads();
#pragma unroll
                for (int it = 0; it < 4; it++) sa.Xs[(it << 2) + kofs][nn] = xr[it];
                sa.Ws[kW][cW] = wr;
                __syncthreads();
                if (ch < 39) {
                    const int kb2 = (ch + 1) << 4;
#pragma unroll
                    for (int it = 0; it < 4; it++) {
                        int kg = kb2 + kofs + (it << 2);
                        xr[it] = (kg < VV) ? __ldcg(&g_ctxT[kg * NB + gn])
                                           : __ldcg(&h1r[(kg - VV) * NB + gn]);
                    }
                    int kg = kb2 + kW;
                    wr = (kg < VV) ? W_ih1[(size_t)caW * 640 + 512 + kg]
                                   : W_hh1[(size_t)caW * 512 + (kg - VV)];
                }
#pragma unroll
                for (int k = 0; k < 16; k++) {
                    float w = sa.Ws[k][col];
                    float4 x = *(const float4*)&sa.Xs[k][ng << 2];
                    acc0 = fmaf(x.x, w, acc0);
                    acc1 = fmaf(x.y, w, acc1);
                    acc2 = fmaf(x.z, w, acc2);
                    acc3 = fmaf(x.w, w, acc3);
                }
            }
            __syncthreads();
            sa.sg[col][(ng << 2) + 0] = acc0;
            sa.sg[col][(ng << 2) + 1] = acc1;
            sa.sg[col][(ng << 2) + 2] = acc2;
            sa.sg[col][(ng << 2) + 3] = acc3;
            __syncthreads();
            const int u = tid >> 6, an = tid & 63;
            float gi = sa.sg[4 * u + 0][an];
            float gf = sa.sg[4 * u + 1][an];
            float gg = sa.sg[4 * u + 2][an];
            float go = sa.sg[4 * u + 3][an];
            int ci = (u0 + u) * NB + nh * 64 + an;
            float cn = sigf(gf) * g_c1T[ci] + sigf(gi) * tanhf(gg);
            g_c1T[ci] = cn;
            g_h1T[(size_t)(p ^ 1) * (HH * NB) + ci] = sigf(go) * tanhf(cn);
        }
        gbar();

        // ===== phase B: LSTM2 gates (4 cols x 128 n, blocks < 128) + apply =====
        if (blk < 128) {
            SB& sb = scr.b;
            const int col = tid & 3, ng = tid >> 2;
            const int nn = tid & 127, kofs = tid >> 7;
            const float* h1r = g_h1T + (size_t)(p ^ 1) * (HH * NB);
            const float* h2r = g_h2T + (size_t)p * (KK * NB);
            float acc0 = 0.0f, acc1 = 0.0f;

            float xr[8];
#pragma unroll
            for (int it = 0; it < 8; it++) {
                int kg = kofs + (it << 1);
                xr[it] = (kg < HH) ? __ldcg(&h1r[kg * NB + nn])
                                   : __ldcg(&h2r[(kg - HH) * NB + nn]);
            }
#pragma unroll 1
            for (int ch = 0; ch < 40; ch++) {
                __syncthreads();
#pragma unroll
                for (int it = 0; it < 8; it++) sb.Xs[(it << 1) + kofs][nn] = xr[it];
                __syncthreads();
                if (ch < 39) {
                    const int kb2 = (ch + 1) << 4;
#pragma unroll
                    for (int it = 0; it < 8; it++) {
                        int kg = kb2 + kofs + (it << 1);
                        xr[it] = (kg < HH) ? __ldcg(&h1r[kg * NB + nn])
                                           : __ldcg(&h2r[(kg - HH) * NB + nn]);
                    }
                }
                const int kb = ch << 4;
#pragma unroll
                for (int k = 0; k < 16; k++) {
                    float w = WsB[col][kb + k];
                    float2 x = *(const float2*)&sb.Xs[k][ng << 1];
                    acc0 = fmaf(x.x, w, acc0);
                    acc1 = fmaf(x.y, w, acc1);
                }
            }
            __syncthreads();
            sb.sg[col][(ng << 1) + 0] = acc0;
            sb.sg[col][(ng << 1) + 1] = acc1;
            __syncthreads();
            if (tid < 128) {
                const int nn2 = tid;
                float gi = sb.sg[0][nn2] + b_ih2[blk]       + b_hh2[blk];
                float gf = sb.sg[1][nn2] + b_ih2[128 + blk] + b_hh2[128 + blk];
                float gg = sb.sg[2][nn2] + b_ih2[256 + blk] + b_hh2[256 + blk];
                float go = sb.sg[3][nn2] + b_ih2[384 + blk] + b_hh2[384 + blk];
                int ci = blk * NB + nn2;
                float cn = sigf(gf) * g_c2T[ci] + sigf(gi) * tanhf(gg);
                g_c2T[ci] = cn;
                g_h2T[(size_t)(p ^ 1) * (KK * NB) + ci] = sigf(go) * tanhf(cn);
            }
        }
        gbar();

        // ===== phase C: balanced flash attention + combine + MoS =====
        {
            SC& sc = scr.c;
            if (tid <= NB) sc.prefix[tid] = g_prefix[tid];
            __syncthreads();
            const long long W = sc.prefix[NB];
            const int r0 = (int)((long long)blk * W / NBLK);
            const int r1 = (int)((long long)(blk + 1) * W / NBLK);
            const int warp = tid >> 5, lane = tid & 31;

            int n0 = 0;
            for (int n = 1; n < NB; n++) { if (sc.prefix[n] <= r0) n0 = n; else break; }

            for (int n = n0; n < NB && sc.prefix[n] < r1; n++) {
                const int Pn = sc.prefix[n], Pn1 = sc.prefix[n + 1];
                const int tlo = max(r0, Pn) - Pn;
                const int thi = min(r1, Pn1) - Pn;
                if (thi <= tlo) continue;

                if (tid < KK)
                    sc.h2s[tid] = __ldcg(&g_h2T[(size_t)(p ^ 1) * (KK * NB) + tid * NB + n]);
                __syncthreads();
                const float4 hv = *(const float4*)&sc.h2s[lane << 2];

                float m = -1e30f, ssum = 0.0f;
                float4 acc = make_float4(0.f, 0.f, 0.f, 0.f);
                const size_t rowstride = (size_t)NB * KK;
                const size_t base = (size_t)n * KK + (lane << 2);

                int t = tlo + warp;
                for (; t + 24 < thi; t += 32) {
                    const __half* kp = g_kb + (size_t)t * rowstride + base;
                    const __half* vp = g_vb + (size_t)t * rowstride + base;
                    uint2 kw0 = *(const uint2*)kp;
                    uint2 kw1 = *(const uint2*)(kp + 8 * rowstride);
                    uint2 kw2 = *(const uint2*)(kp + 16 * rowstride);
                    uint2 kw3 = *(const uint2*)(kp + 24 * rowstride);
                    uint2 vw0 = *(const uint2*)vp;
                    uint2 vw1 = *(const uint2*)(vp + 8 * rowstride);
                    uint2 vw2 = *(const uint2*)(vp + 16 * rowstride);
                    uint2 vw3 = *(const uint2*)(vp + 24 * rowstride);
                    float2 a0 = __half22float2(*(__half2*)&kw0.x);
                    float2 b0 = __half22float2(*(__half2*)&kw0.y);
                    float2 a1 = __half22float2(*(__half2*)&kw1.x);
                    float2 b1 = __half22float2(*(__half2*)&kw1.y);
                    float2 a2 = __half22float2(*(__half2*)&kw2.x);
                    float2 b2 = __half22float2(*(__half2*)&kw2.y);
                    float2 a3 = __half22float2(*(__half2*)&kw3.x);
                    float2 b3 = __half22float2(*(__half2*)&kw3.y);
                    float d0 = a0.x * hv.x + a0.y * hv.y + b0.x * hv.z + b0.y * hv.w;
                    float d1 = a1.x * hv.x + a1.y * hv.y + b1.x * hv.z + b1.y * hv.w;
                    float d2 = a2.x * hv.x + a2.y * hv.y + b2.x * hv.z + b2.y * hv.w;
                    float d3 = a3.x * hv.x + a3.y * hv.y + b3.x * hv.z + b3.y * hv.w;
#pragma unroll
                    for (int o = 16; o; o >>= 1) {
                        d0 += __shfl_xor_sync(0xffffffffu, d0, o);
                        d1 += __shfl_xor_sync(0xffffffffu, d1, o);
                        d2 += __shfl_xor_sync(0xffffffffu, d2, o);
                        d3 += __shfl_xor_sync(0xffffffffu, d3, o);
                    }
                    float mx = fmaxf(fmaxf(d0, d1), fmaxf(d2, d3));
                    float mn = fmaxf(m, mx);
                    float scale = __expf(m - mn);
                    float p0 = __expf(d0 - mn), p1 = __expf(d1 - mn);
                    float p2 = __expf(d2 - mn), p3 = __expf(d3 - mn);
                    ssum = ssum * scale + ((p0 + p1) + (p2 + p3));
                    float2 va0 = __half22float2(*(__half2*)&vw0.x);
                    float2 vb0 = __half22float2(*(__half2*)&vw0.y);
                    float2 va1 = __half22float2(*(__half2*)&vw1.x);
                    float2 vb1 = __half22float2(*(__half2*)&vw1.y);
                    float2 va2 = __half22float2(*(__half2*)&vw2.x);
                    float2 vb2 = __half22float2(*(__half2*)&vw2.y);
                    float2 va3 = __half22float2(*(__half2*)&vw3.x);
                    float2 vb3 = __half22float2(*(__half2*)&vw3.y);
                    acc.x = acc.x * scale + p0 * va0.x + p1 * va1.x + p2 * va2.x + p3 * va3.x;
                    acc.y = acc.y * scale + p0 * va0.y + p1 * va1.y + p2 * va2.y + p3 * va3.y;
                    acc.z = acc.z * scale + p0 * vb0.x + p1 * vb1.x + p2 * vb2.x + p3 * vb3.x;
                    acc.w = acc.w * scale + p0 * vb0.y + p1 * vb1.y + p2 * vb2.y + p3 * vb3.y;
                    m = mn;
                }
                for (; t < thi; t += 8) {
                    const __half* kp = g_kb + (size_t)t * rowstride + base;
                    const __half* vp = g_vb + (size_t)t * rowstride + base;
                    uint2 kw = *(const uint2*)kp;
                    uint2 vw = *(const uint2*)vp;
                    float2 a0 = __half22float2(*(__half2*)&kw.x);
                    float2 b0 = __half22float2(*(__half2*)&kw.y);
                    float d = a0.x * hv.x + a0.y * hv.y + b0.x * hv.z + b0.y * hv.w;
#pragma unroll
                    for (int o = 16; o; o >>= 1) d += __shfl_xor_sync(0xffffffffu, d, o);
                    float mn = fmaxf(m, d);
                    float scale = __expf(m - mn);
                    float pp = __expf(d - mn);
                    ssum = ssum * scale + pp;
                    float2 va = __half22float2(*(__half2*)&vw.x);
                    float2 vb = __half22float2(*(__half2*)&vw.y);
                    acc.x = acc.x * scale + pp * va.x;
                    acc.y = acc.y * scale + pp * va.y;
                    acc.z = acc.z * scale + pp * vb.x;
                    acc.w = acc.w * scale + pp * vb.y;
                    m = mn;
                }

                if (lane == 0) { sc.wm[warp] = m; sc.wsum[warp] = ssum; }
                *(float4*)&sc.wacc[warp][lane << 2] = acc;
                __syncthreads();

                const int slot = blk - g_bfirst[n];
                if (tid < VV) {
                    float mm = -1e30f;
#pragma unroll
                    for (int w = 0; w < 8; w++) mm = fmaxf(mm, sc.wm[w]);
                    float S = 0.0f, C = 0.0f;
#pragma unroll
                    for (int w = 0; w < 8; w++) {
                        float e = __expf(sc.wm[w] - mm);
                        S += e * sc.wsum[w];
                        C += e * sc.wacc[w][tid];
                    }
                    g_pacc[((size_t)n * NBLK + slot) * VV + tid] = C;
                    if (tid == 0) { g_pm[n * NBLK + slot] = mm; g_ps[n * NBLK + slot] = S; }
                    __threadfence();
                }
                __syncthreads();
                if (tid == 0) {
                    int old = atomicAdd(&g_acnt[n], 1);
                    __threadfence();
                    sc.flag = (old == g_bcnt[n] - 1);
                }
                __syncthreads();
                if (sc.flag) {
                    const int bf = g_bfirst[n], bl = g_blast[n];
                    if (tid < VV) {
                        float mm = -1e30f;
                        for (int bb = bf; bb <= bl; bb++) {
                            int rr0 = (int)((long long)bb * W / NBLK);
                            int rr1 = (int)((long long)(bb + 1) * W / NBLK);
                            if (max(rr0, Pn) < min(rr1, Pn1))
                                mm = fmaxf(mm, __ldcg(&g_pm[n * NBLK + (bb - bf)]));
                        }
                        float S = 0.0f, C = 0.0f;
                        for (int bb = bf; bb <= bl; bb++) {
                            int rr0 = (int)((long long)bb * W / NBLK);
                            int rr1 = (int)((long long)(bb + 1) * W / NBLK);
                            if (max(rr0, Pn) < min(rr1, Pn1)) {
                                int s2 = bb - bf;
                                float e = __expf(__ldcg(&g_pm[n * NBLK + s2]) - mm);
                                S += e * __ldcg(&g_ps[n * NBLK + s2]);
                                C += e * __ldcg(&g_pacc[((size_t)n * NBLK + s2) * VV + tid]);
                            }
                        }
                        float cv = C / S;
                        sc.ctxs[tid] = cv;
                        g_ctxT[tid * NB + n] = cv;
                    }
                    if (tid == 0) g_acnt[n] = 0;
                    __syncthreads();
                    if (tid < AA) {
                        float a = b_mos[tid];
                        const float* w = W_mos + (size_t)tid * (KK + VV);
#pragma unroll 4
                        for (int k = 0; k < KK; k++) a = fmaf(sc.h2s[k], w[k], a);
#pragma unroll 4
                        for (int v = 0; v < VV; v++) a = fmaf(sc.ctxs[v], w[KK + v], a);
                        out[((size_t)n * LL + l) * AA + tid] = a;
                    }
                }
                __syncthreads();
            }
        }
        gbar();
    }
}

// ---------------- launch ----------------
extern "C" void kernel_launch(void* const* d_in, const int* in_sizes, int n_in,
                              void* d_out, int out_size) {
    (void)in_sizes; (void)n_in; (void)out_size;
    const float* key    = (const float*)d_in[0];
    const float* values = (const float*)d_in[1];
    const int*   lens   = (const int*)  d_in[2];
    const int*   text   = (const int*)  d_in[3];
    const float* emb    = (const float*)d_in[4];
    const float* W_ih1  = (const float*)d_in[5];
    const float* W_hh1  = (const float*)d_in[6];
    const float* b_ih1  = (const float*)d_in[7];
    const float* b_hh1  = (const float*)d_in[8];
    const float* W_ih2  = (const float*)d_in[9];
    const float* W_hh2  = (const float*)d_in[10];
    const float* b_ih2  = (const float*)d_in[11];
    const float* b_hh2  = (const float*)d_in[12];
    const float* W_mos  = (const float*)d_in[13];
    const float* b_mos  = (const float*)d_in[14];
    float* out = (float*)d_out;

    init_kernel<<<256, 256>>>(values);
    meta_kernel<<<1, 256>>>(lens);
    conv_kernel<<<4096, 256>>>(key, values);
    pb_kernel<<<64, 256>>>(emb, W_ih1, b_ih1, b_hh1);
    decoder_main<<<NBLK, NTHR>>>(text, W_ih1, W_hh1, W_ih2, W_hh2,
                                 b_ih2, b_hh2, W_mos, b_mos, out);
}